// round 8
// baseline (speedup 1.0000x reference)
#include <cuda_runtime.h>
#include <cstdint>

#define Nn   2048
#define IND  128
#define HIDD 64
#define Ee   32768
#define EPSf 1e-5f
#define NOUT 4096   /* HIDD*HIDD */

// -------- scratch (device globals; no allocation allowed) --------
__device__ __align__(256) float g_p1[Nn * NOUT];     // relu(h@W1+b1)
__device__ __align__(256) float g_p2[Nn * HIDD];     // relu(h@Wp2+bp2)
__device__ __align__(256) float g_u[Nn * IND];       // src-half conv of LN(local)
__device__ __align__(256) float g_v[Nn * IND];       // dst-half conv of LN(local)
__device__ __align__(256) uint32_t g_wghi[HIDD * HIDD];  // tf32 split of Wg
__device__ __align__(256) uint32_t g_wglo[HIDD * HIDD];
__device__ __align__(256) uint32_t g_w2hi[IND * HIDD];   // tf32 split of W2
__device__ __align__(256) uint32_t g_w2lo[IND * HIDD];
__device__ __align__(256) float g_C[HIDD];
__device__ int g_off[Nn + 1];
__device__ int g_eidx[Ee];

// ================= tf32 helpers =================
__device__ __forceinline__ uint32_t f2tf(float x) {
    uint32_t r;
    asm("cvt.rna.tf32.f32 %0, %1;" : "=r"(r) : "f"(x));
    return r;
}
__device__ __forceinline__ void mma_tf32(float* d, const uint32_t* a, const uint32_t* b) {
    asm volatile(
        "mma.sync.aligned.m16n8k8.row.col.f32.tf32.tf32.f32 "
        "{%0,%1,%2,%3}, {%4,%5,%6,%7}, {%8,%9}, {%0,%1,%2,%3};"
        : "+f"(d[0]), "+f"(d[1]), "+f"(d[2]), "+f"(d[3])
        : "r"(a[0]), "r"(a[1]), "r"(a[2]), "r"(a[3]), "r"(b[0]), "r"(b[1]));
}

// ================= fused bucketing: hist + scan + scatter, one block =================
__global__ __launch_bounds__(1024) void k_bucket(const int* __restrict__ src) {
    __shared__ int cnt[Nn];
    __shared__ int warpsum[32];
    int t = threadIdx.x;
    cnt[t] = 0;
    cnt[t + 1024] = 0;
    __syncthreads();
    for (int e = t; e < Ee; e += 1024) atomicAdd(&cnt[src[e]], 1);
    __syncthreads();

    int c0 = cnt[2 * t], c1 = cnt[2 * t + 1];
    int s = c0 + c1;
    int lane = t & 31, warp = t >> 5;
    int v = s;
#pragma unroll
    for (int o = 1; o < 32; o <<= 1) {
        int u = __shfl_up_sync(0xffffffffu, v, o);
        if (lane >= o) v += u;
    }
    if (lane == 31) warpsum[warp] = v;
    __syncthreads();
    if (warp == 0) {
        int w = warpsum[lane];
#pragma unroll
        for (int o = 1; o < 32; o <<= 1) {
            int u = __shfl_up_sync(0xffffffffu, w, o);
            if (lane >= o) w += u;
        }
        warpsum[lane] = w;
    }
    __syncthreads();
    int excl = v - s + (warp ? warpsum[warp - 1] : 0);
    g_off[2 * t] = excl;
    g_off[2 * t + 1] = excl + c0;
    if (t == 1023) g_off[Nn] = excl + s;
    __syncthreads();
    cnt[2 * t] = excl;
    cnt[2 * t + 1] = excl + c0;
    __syncthreads();
    for (int e = t; e < Ee; e += 1024) {
        int p = atomicAdd(&cnt[src[e]], 1);
        g_eidx[p] = e;
    }
}

// ================= prep: Wg split + C + W2 split =================
__global__ void k_prep(const float* __restrict__ W3,
                       const float* __restrict__ b3,
                       const float* __restrict__ bng_g,
                       const float* __restrict__ bng_b,
                       const float* __restrict__ bnG_g,
                       const float* __restrict__ bnG_b,
                       const float* __restrict__ W2) {
    int idx = blockIdx.x * blockDim.x + threadIdx.x;
    float rs = rsqrtf(1.f + EPSf);
    if (idx < 4096) {
        int d = idx >> 6, dp = idx & 63;
        float wg = (bng_g[d] * rs) * W3[idx] * (bnG_g[dp] * rs);
        uint32_t hi = f2tf(wg);
        g_wghi[idx] = hi;
        g_wglo[idx] = f2tf(wg - __uint_as_float(hi));
    } else if (idx < 4096 + 8192) {
        int j = idx - 4096;
        float w = W2[j];
        uint32_t hi = f2tf(w);
        g_w2hi[j] = hi;
        g_w2lo[j] = f2tf(w - __uint_as_float(hi));
    } else if (idx < 4096 + 8192 + 64) {
        int dp = idx - 12288;
        float s = 0.f;
        for (int d = 0; d < 64; d++) s += bng_b[d] * W3[d * 64 + dp];
        g_C[dp] = (s + b3[dp]) * (bnG_g[dp] * rs) + bnG_b[dp];
    }
}

// ================= node prep: LN(local[i]) -> u[i], v[i] =================
__global__ __launch_bounds__(256) void k_nodeprep(const float* __restrict__ local,
                                                  const float* __restrict__ ln_w,
                                                  const float* __restrict__ ln_b,
                                                  const float* __restrict__ conv_w) {
    __shared__ float lns[2][IND + 2];
    __shared__ float2 red[2][4];
    int tid = threadIdx.x;
    int grp = tid >> 7, t = tid & 127;
    int node = blockIdx.x * 2 + grp;
    int lane = t & 31, warp = t >> 5;

    float x = local[node * IND + t];
    float2 v = make_float2(x, x * x);
#pragma unroll
    for (int o = 16; o; o >>= 1) {
        v.x += __shfl_down_sync(0xffffffffu, v.x, o);
        v.y += __shfl_down_sync(0xffffffffu, v.y, o);
    }
    if (lane == 0) red[grp][warp] = v;
    if (t == 0) { lns[grp][0] = 0.f; lns[grp][IND + 1] = 0.f; }
    __syncthreads();
    float2 tot = red[grp][0];
    tot.x += red[grp][1].x + red[grp][2].x + red[grp][3].x;
    tot.y += red[grp][1].y + red[grp][2].y + red[grp][3].y;
    float mu = tot.x * (1.f / IND);
    float var = tot.y * (1.f / IND) - mu * mu;
    float ln = (x - mu) * rsqrtf(var + EPSf) * ln_w[t] + ln_b[t];
    lns[grp][t + 1] = ln;
    __syncthreads();
    float l0 = lns[grp][t], l1 = lns[grp][t + 1], l2 = lns[grp][t + 2];
    g_u[node * IND + t] = conv_w[0] * l0 + conv_w[1] * l1 + conv_w[2] * l2;
    g_v[node * IND + t] = conv_w[3] * l0 + conv_w[4] * l1 + conv_w[5] * l2;
}

// ================= p1 = relu(h@W1+b1) (+fused p2 tile) via 3xTF32 mma =================
#define ASTR 68
#define BSTR 136
#define KC   64
#define P1_SMEM ((128 * ASTR + KC * BSTR) * 4)

__global__ __launch_bounds__(256) void k_p1tf(const float* __restrict__ h,
                                              const float* __restrict__ W1,
                                              const float* __restrict__ b1,
                                              const float* __restrict__ Wp2,
                                              const float* __restrict__ bp2) {
    extern __shared__ float sm[];
    float* As = sm;
    float* Bs = sm + 128 * ASTR;

    int tid = threadIdx.x;
    int wid = tid >> 5, lane = tid & 31;
    int g = lane >> 2, t = lane & 3;
    int warp_m = (wid >> 2) * 64;
    int warp_n = (wid & 3) * 32;
    int bx = blockIdx.x;
    int row0 = blockIdx.y * 128;
    int col0 = bx * 128;
    bool p2tile = (bx == 32);

    float acc[4][4][4];
#pragma unroll
    for (int mi = 0; mi < 4; mi++)
#pragma unroll
        for (int ni = 0; ni < 4; ni++)
#pragma unroll
            for (int r = 0; r < 4; r++) acc[mi][ni][r] = 0.f;

    for (int kc = 0; kc < IND; kc += KC) {
#pragma unroll
        for (int it = 0; it < 8; it++) {
            int chunk = tid + it * 256;
            int m = chunk >> 4;
            int k4 = (chunk & 15) * 4;
            float4 v = *(const float4*)&h[(row0 + m) * IND + kc + k4];
            *(float4*)&As[m * ASTR + k4] = v;
        }
#pragma unroll
        for (int it = 0; it < 8; it++) {
            int chunk = tid + it * 256;
            int k = chunk >> 5;
            int n4 = (chunk & 31) * 4;
            float4 v;
            if (!p2tile) {
                v = *(const float4*)&W1[(kc + k) * NOUT + col0 + n4];
            } else if (n4 < 64) {
                v = *(const float4*)&Wp2[(kc + k) * HIDD + n4];
            } else {
                v = make_float4(0.f, 0.f, 0.f, 0.f);
            }
            *(float4*)&Bs[k * BSTR + n4] = v;
        }
        __syncthreads();

#pragma unroll
        for (int ks = 0; ks < KC; ks += 8) {
            uint32_t ahi[4][4], alo[4][4], bhi[4][2], blo[4][2];
#pragma unroll
            for (int mi = 0; mi < 4; mi++) {
                int r = warp_m + mi * 16 + g;
                float a0 = As[r * ASTR + ks + t];
                float a1 = As[(r + 8) * ASTR + ks + t];
                float a2 = As[r * ASTR + ks + t + 4];
                float a3 = As[(r + 8) * ASTR + ks + t + 4];
                ahi[mi][0] = f2tf(a0); alo[mi][0] = f2tf(a0 - __uint_as_float(ahi[mi][0]));
                ahi[mi][1] = f2tf(a1); alo[mi][1] = f2tf(a1 - __uint_as_float(ahi[mi][1]));
                ahi[mi][2] = f2tf(a2); alo[mi][2] = f2tf(a2 - __uint_as_float(ahi[mi][2]));
                ahi[mi][3] = f2tf(a3); alo[mi][3] = f2tf(a3 - __uint_as_float(ahi[mi][3]));
            }
#pragma unroll
            for (int ni = 0; ni < 4; ni++) {
                int n = warp_n + ni * 8 + g;
                float b0 = Bs[(ks + t) * BSTR + n];
                float b1v = Bs[(ks + t + 4) * BSTR + n];
                bhi[ni][0] = f2tf(b0);  blo[ni][0] = f2tf(b0 - __uint_as_float(bhi[ni][0]));
                bhi[ni][1] = f2tf(b1v); blo[ni][1] = f2tf(b1v - __uint_as_float(bhi[ni][1]));
            }
#pragma unroll
            for (int mi = 0; mi < 4; mi++)
#pragma unroll
                for (int ni = 0; ni < 4; ni++) {
                    mma_tf32(acc[mi][ni], ahi[mi], bhi[ni]);
                    mma_tf32(acc[mi][ni], ahi[mi], blo[ni]);
                    mma_tf32(acc[mi][ni], alo[mi], bhi[ni]);
                }
        }
        __syncthreads();
    }

    if (!p2tile) {
#pragma unroll
        for (int mi = 0; mi < 4; mi++) {
            int r = row0 + warp_m + mi * 16 + g;
#pragma unroll
            for (int ni = 0; ni < 4; ni++) {
                int c = col0 + warp_n + ni * 8 + t * 2;
                float2 bb = *(const float2*)&b1[c];
                float2 o0, o1;
                o0.x = fmaxf(acc[mi][ni][0] + bb.x, 0.f);
                o0.y = fmaxf(acc[mi][ni][1] + bb.y, 0.f);
                o1.x = fmaxf(acc[mi][ni][2] + bb.x, 0.f);
                o1.y = fmaxf(acc[mi][ni][3] + bb.y, 0.f);
                *(float2*)&g_p1[(size_t)r * NOUT + c] = o0;
                *(float2*)&g_p1[(size_t)(r + 8) * NOUT + c] = o1;
            }
        }
    } else {
#pragma unroll
        for (int mi = 0; mi < 4; mi++) {
            int r = row0 + warp_m + mi * 16 + g;
#pragma unroll
            for (int ni = 0; ni < 4; ni++) {
                int c = warp_n + ni * 8 + t * 2;
                if (c < HIDD) {
                    float2 bb = *(const float2*)&bp2[c];
                    float2 o0, o1;
                    o0.x = fmaxf(acc[mi][ni][0] + bb.x, 0.f);
                    o0.y = fmaxf(acc[mi][ni][1] + bb.y, 0.f);
                    o1.x = fmaxf(acc[mi][ni][2] + bb.x, 0.f);
                    o1.y = fmaxf(acc[mi][ni][3] + bb.y, 0.f);
                    *(float2*)&g_p2[r * HIDD + c] = o0;
                    *(float2*)&g_p2[(r + 8) * HIDD + c] = o1;
                }
            }
        }
    }
}

// ================= local branch v2: gather u+v, relu, mma @W2, epilogue =================
#define TSTR 132
#define W2STR 72
#define LO_T   0
#define LO_W2H (32 * TSTR * 4)               /* 16896 */
#define LO_W2L (LO_W2H + 128 * W2STR * 4)    /* +36864 */
#define L2_SMEM (LO_W2L + 128 * W2STR * 4)

__global__ __launch_bounds__(256) void k_local2(const int* __restrict__ src,
                                                const int* __restrict__ dst,
                                                const float* __restrict__ conv_b,
                                                const float* __restrict__ b2,
                                                const float* __restrict__ bnL_g,
                                                const float* __restrict__ bnL_b,
                                                const float* __restrict__ ein,
                                                float* __restrict__ out) {
    extern __shared__ char smraw[];
    float* Ts = (float*)(smraw + LO_T);            // [32][TSTR]
    uint32_t* W2h = (uint32_t*)(smraw + LO_W2H);   // [128][W2STR]
    uint32_t* W2l = (uint32_t*)(smraw + LO_W2L);

    int tid = threadIdx.x;
    int e0 = blockIdx.x * 32;
    float cb = conv_b[0];

    // build T = relu(u[src] + v[dst] + cb)
#pragma unroll
    for (int it = 0; it < 16; it++) {
        int idx = tid + it * 256;                  // e*128 + t
        int e = idx >> 7, t = idx & 127;
        int se = src[e0 + e], de = dst[e0 + e];
        float val = g_u[se * IND + t] + g_v[de * IND + t] + cb;
        Ts[e * TSTR + t] = fmaxf(val, 0.f);
    }
    // load split W2
#pragma unroll
    for (int it = 0; it < 32; it++) {
        int idx = tid + it * 256;                  // k*64 + n
        int k = idx >> 6, n = idx & 63;
        W2h[k * W2STR + n] = g_w2hi[idx];
        W2l[k * W2STR + n] = g_w2lo[idx];
    }
    __syncthreads();

    // mma: T[32x128] @ W2[128x64]; 8 warps, warp tile 16x16
    int wid = tid >> 5, lane = tid & 31;
    int g = lane >> 2, t = lane & 3;
    int m0 = (wid & 1) * 16;
    int n0 = (wid >> 1) * 16;

    float acc[2][4];
#pragma unroll
    for (int ni = 0; ni < 2; ni++)
#pragma unroll
        for (int r = 0; r < 4; r++) acc[ni][r] = 0.f;

#pragma unroll
    for (int ks = 0; ks < 128; ks += 8) {
        uint32_t ahi[4], alo[4], bh[2][2], bl[2][2];
        int r = m0 + g;
        float a0 = Ts[r * TSTR + ks + t];
        float a1 = Ts[(r + 8) * TSTR + ks + t];
        float a2 = Ts[r * TSTR + ks + t + 4];
        float a3 = Ts[(r + 8) * TSTR + ks + t + 4];
        ahi[0] = f2tf(a0); alo[0] = f2tf(a0 - __uint_as_float(ahi[0]));
        ahi[1] = f2tf(a1); alo[1] = f2tf(a1 - __uint_as_float(ahi[1]));
        ahi[2] = f2tf(a2); alo[2] = f2tf(a2 - __uint_as_float(ahi[2]));
        ahi[3] = f2tf(a3); alo[3] = f2tf(a3 - __uint_as_float(ahi[3]));
#pragma unroll
        for (int ni = 0; ni < 2; ni++) {
            int n = n0 + ni * 8 + g;
            bh[ni][0] = W2h[(ks + t) * W2STR + n];
            bh[ni][1] = W2h[(ks + t + 4) * W2STR + n];
            bl[ni][0] = W2l[(ks + t) * W2STR + n];
            bl[ni][1] = W2l[(ks + t + 4) * W2STR + n];
        }
#pragma unroll
        for (int ni = 0; ni < 2; ni++) {
            mma_tf32(acc[ni], ahi, bh[ni]);
            mma_tf32(acc[ni], ahi, bl[ni]);
            mma_tf32(acc[ni], alo, bh[ni]);
        }
    }

    float rs = rsqrtf(1.f + EPSf);
    int ea = e0 + m0 + g, eb = ea + 8;
#pragma unroll
    for (int ni = 0; ni < 2; ni++) {
        int c = n0 + ni * 8 + t * 2;
        float2 bb = *(const float2*)&b2[c];
        float2 gg = *(const float2*)&bnL_g[c];
        float2 bL = *(const float2*)&bnL_b[c];
        float2 ia = *(const float2*)&ein[ea * HIDD + c];
        float2 ib = *(const float2*)&ein[eb * HIDD + c];
        float2 oa, ob;
        oa.x = fmaxf((acc[ni][0] + bb.x) * (gg.x * rs) + bL.x, 0.f) + ia.x;
        oa.y = fmaxf((acc[ni][1] + bb.y) * (gg.y * rs) + bL.y, 0.f) + ia.y;
        ob.x = fmaxf((acc[ni][2] + bb.x) * (gg.x * rs) + bL.x, 0.f) + ib.x;
        ob.y = fmaxf((acc[ni][3] + bb.y) * (gg.y * rs) + bL.y, 0.f) + ib.y;
        *(float2*)&out[ea * HIDD + c] = oa;
        *(float2*)&out[eb * HIDD + c] = ob;
    }
}

// ================= global branch fused, latency-optimized =================
#define GA_STR 68
#define ECAP 64
#define GO_AS  0
#define GO_BHI (64 * GA_STR * 4)
#define GO_BLO (GO_BHI + 64 * 72 * 4)
#define GO_P2  (GO_BLO + 64 * 72 * 4)
#define GO_EIX (GO_P2 + ECAP * 64 * 4)
#define G2_SMEM (GO_EIX + ECAP * 4)

__global__ __launch_bounds__(256) void k_global2(const int* __restrict__ dst,
                                                 float* __restrict__ out) {
    extern __shared__ char smraw[];
    float* As = (float*)(smraw + GO_AS);
    float* Gs = As;
    uint32_t* Bhi = (uint32_t*)(smraw + GO_BHI);
    uint32_t* Blo = (uint32_t*)(smraw + GO_BLO);
    float* p2buf = (float*)(smraw + GO_P2);
    int* eixs = (int*)(smraw + GO_EIX);

    int node = blockIdx.x;
    int tid = threadIdx.x;
    int beg = g_off[node], end = g_off[node + 1];
    if (beg == end) return;

    int ec = min(end - beg, ECAP);
    for (int idx = tid; idx < ec * 64; idx += 256) {
        int ei = idx >> 6, d2 = idx & 63;
        int e = g_eidx[beg + ei];
        if (d2 == 0) eixs[ei] = e;
        p2buf[idx] = g_p2[dst[e] * HIDD + d2];
    }

    const float* p1row = &g_p1[(size_t)node * NOUT];
#pragma unroll
    for (int it = 0; it < 16; it++) {
        int idx = tid + it * 256;
        int d = idx >> 6, k = idx & 63;
        As[k * GA_STR + d] = p1row[idx];
    }
#pragma unroll
    for (int it = 0; it < 16; it++) {
        int idx = tid + it * 256;
        int d = idx >> 6, dp = idx & 63;
        Bhi[d * 72 + dp] = g_wghi[idx];
        Blo[d * 72 + dp] = g_wglo[idx];
    }
    __syncthreads();

    int wid = tid >> 5, lane = tid & 31;
    int g = lane >> 2, t = lane & 3;
    int m0 = (wid & 3) * 16;
    int n0 = (wid >> 2) * 32;

    float acc[4][4];
#pragma unroll
    for (int ni = 0; ni < 4; ni++)
#pragma unroll
        for (int r = 0; r < 4; r++) acc[ni][r] = 0.f;

#pragma unroll
    for (int ks = 0; ks < 64; ks += 8) {
        uint32_t ahi[4], alo[4], bh[4][2], bl[4][2];
        int r = m0 + g;
        float a0 = As[r * GA_STR + ks + t];
        float a1 = As[(r + 8) * GA_STR + ks + t];
        float a2 = As[r * GA_STR + ks + t + 4];
        float a3 = As[(r + 8) * GA_STR + ks + t + 4];
        ahi[0] = f2tf(a0); alo[0] = f2tf(a0 - __uint_as_float(ahi[0]));
        ahi[1] = f2tf(a1); alo[1] = f2tf(a1 - __uint_as_float(ahi[1]));
        ahi[2] = f2tf(a2); alo[2] = f2tf(a2 - __uint_as_float(ahi[2]));
        ahi[3] = f2tf(a3); alo[3] = f2tf(a3 - __uint_as_float(ahi[3]));
#pragma unroll
        for (int ni = 0; ni < 4; ni++) {
            int n = n0 + ni * 8 + g;
            bh[ni][0] = Bhi[(ks + t) * 72 + n];
            bh[ni][1] = Bhi[(ks + t + 4) * 72 + n];
            bl[ni][0] = Blo[(ks + t) * 72 + n];
            bl[ni][1] = Blo[(ks + t + 4) * 72 + n];
        }
#pragma unroll
        for (int ni = 0; ni < 4; ni++) {
            mma_tf32(acc[ni], ahi, bh[ni]);
            mma_tf32(acc[ni], ahi, bl[ni]);
            mma_tf32(acc[ni], alo, bh[ni]);
        }
    }
    __syncthreads();

    int m = m0 + g;
#pragma unroll
    for (int ni = 0; ni < 4; ni++) {
        int n = n0 + ni * 8 + t * 2;
        Gs[m * 65 + n] = acc[ni][0];
        Gs[m * 65 + n + 1] = acc[ni][1];
        Gs[(m + 8) * 65 + n] = acc[ni][2];
        Gs[(m + 8) * 65 + n + 1] = acc[ni][3];
    }
    __syncthreads();

    int d = tid & 63, grp = tid >> 6;
    float Gr[64];
#pragma unroll
    for (int k = 0; k < 64; k++) Gr[k] = Gs[k * 65 + d];
    float Cd = g_C[d];

    int base = beg;
    while (true) {
        for (int e = grp; e < ec; e += 4) {
            const float4* p = (const float4*)&p2buf[e * 64];
            float a2 = 0.f;
#pragma unroll
            for (int k4 = 0; k4 < 16; k4++) {
                float4 v = p[k4];
                a2 += Gr[k4 * 4 + 0] * v.x + Gr[k4 * 4 + 1] * v.y
                    + Gr[k4 * 4 + 2] * v.z + Gr[k4 * 4 + 3] * v.w;
            }
            int eg = eixs[e];
            out[eg * HIDD + d] += fmaxf(a2 + Cd, 0.f);
        }
        base += ec;
        if (base >= end) break;
        __syncthreads();
        ec = min(end - base, ECAP);
        for (int idx = tid; idx < ec * 64; idx += 256) {
            int ei = idx >> 6, d2 = idx & 63;
            int e = g_eidx[base + ei];
            if (d2 == 0) eixs[ei] = e;
            p2buf[idx] = g_p2[dst[e] * HIDD + d2];
        }
        __syncthreads();
    }
}

// ================= launch =================
extern "C" void kernel_launch(void* const* d_in, const int* in_sizes, int n_in,
                              void* d_out, int out_size) {
    const float* h      = (const float*)d_in[0];
    const float* local_ = (const float*)d_in[1];
    const float* ein    = (const float*)d_in[2];
    const int*   src    = (const int*)d_in[3];
    const int*   dst    = (const int*)d_in[4];
    const float* ln_w   = (const float*)d_in[5];
    const float* ln_b   = (const float*)d_in[6];
    const float* conv_w = (const float*)d_in[7];
    const float* conv_b = (const float*)d_in[8];
    const float* W1     = (const float*)d_in[9];
    const float* b1     = (const float*)d_in[10];
    const float* Wp2    = (const float*)d_in[11];
    const float* bp2    = (const float*)d_in[12];
    const float* W2     = (const float*)d_in[13];
    const float* b2     = (const float*)d_in[14];
    const float* W3     = (const float*)d_in[15];
    const float* b3     = (const float*)d_in[16];
    const float* bng_g  = (const float*)d_in[17];
    const float* bng_b  = (const float*)d_in[18];
    const float* bnG_g  = (const float*)d_in[19];
    const float* bnG_b  = (const float*)d_in[20];
    const float* bnL_g  = (const float*)d_in[21];
    const float* bnL_b  = (const float*)d_in[22];
    float* out = (float*)d_out;

    static int smem_set = 0;
    if (!smem_set) {
        cudaFuncSetAttribute(k_p1tf, cudaFuncAttributeMaxDynamicSharedMemorySize, P1_SMEM);
        cudaFuncSetAttribute(k_local2, cudaFuncAttributeMaxDynamicSharedMemorySize, L2_SMEM);
        cudaFuncSetAttribute(k_global2, cudaFuncAttributeMaxDynamicSharedMemorySize, G2_SMEM);
        smem_set = 1;
    }

    k_bucket<<<1, 1024>>>(src);
    k_prep<<<49, 256>>>(W3, b3, bng_g, bng_b, bnG_g, bnG_b, W2);
    k_nodeprep<<<Nn / 2, 256>>>(local_, ln_w, ln_b, conv_w);
    k_p1tf<<<dim3(33, Nn / 128), 256, P1_SMEM>>>(h, W1, b1, Wp2, bp2);  // 4th -> profiled
    k_local2<<<Ee / 32, 256, L2_SMEM>>>(src, dst, conv_b, b2, bnL_g, bnL_b, ein, out);
    k_global2<<<Nn, 256, G2_SMEM>>>(dst, out);
}

// round 9
// speedup vs baseline: 1.3042x; 1.3042x over previous
#include <cuda_runtime.h>
#include <cstdint>

#define Nn   2048
#define IND  128
#define HIDD 64
#define Ee   32768
#define EPSf 1e-5f
#define NOUT 4096   /* HIDD*HIDD */

// -------- scratch (device globals; no allocation allowed) --------
__device__ __align__(256) float g_p1[Nn * NOUT];     // relu(h@W1+b1)
__device__ __align__(256) float g_p2[Nn * HIDD];     // relu(h@Wp2+bp2)
__device__ __align__(256) float g_u[Nn * IND];       // src-half conv of LN(local)
__device__ __align__(256) float g_v[Nn * IND];       // dst-half conv of LN(local)
__device__ __align__(256) uint32_t g_wghi[HIDD * HIDD];  // tf32 split of Wg
__device__ __align__(256) uint32_t g_wglo[HIDD * HIDD];
__device__ __align__(256) float g_C[HIDD];
__device__ int g_off[Nn + 1];
__device__ int g_eidx[Ee];

// ================= tf32 helpers =================
__device__ __forceinline__ uint32_t f2tf(float x) {
    uint32_t r;
    asm("cvt.rna.tf32.f32 %0, %1;" : "=r"(r) : "f"(x));
    return r;
}
__device__ __forceinline__ void mma_tf32(float* d, const uint32_t* a, const uint32_t* b) {
    asm volatile(
        "mma.sync.aligned.m16n8k8.row.col.f32.tf32.tf32.f32 "
        "{%0,%1,%2,%3}, {%4,%5,%6,%7}, {%8,%9}, {%0,%1,%2,%3};"
        : "+f"(d[0]), "+f"(d[1]), "+f"(d[2]), "+f"(d[3])
        : "r"(a[0]), "r"(a[1]), "r"(a[2]), "r"(a[3]), "r"(b[0]), "r"(b[1]));
}

// ================= fused bucketing =================
__global__ __launch_bounds__(1024) void k_bucket(const int* __restrict__ src) {
    __shared__ int cnt[Nn];
    __shared__ int warpsum[32];
    int t = threadIdx.x;
    cnt[t] = 0;
    cnt[t + 1024] = 0;
    __syncthreads();
    for (int e = t; e < Ee; e += 1024) atomicAdd(&cnt[src[e]], 1);
    __syncthreads();

    int c0 = cnt[2 * t], c1 = cnt[2 * t + 1];
    int s = c0 + c1;
    int lane = t & 31, warp = t >> 5;
    int v = s;
#pragma unroll
    for (int o = 1; o < 32; o <<= 1) {
        int u = __shfl_up_sync(0xffffffffu, v, o);
        if (lane >= o) v += u;
    }
    if (lane == 31) warpsum[warp] = v;
    __syncthreads();
    if (warp == 0) {
        int w = warpsum[lane];
#pragma unroll
        for (int o = 1; o < 32; o <<= 1) {
            int u = __shfl_up_sync(0xffffffffu, w, o);
            if (lane >= o) w += u;
        }
        warpsum[lane] = w;
    }
    __syncthreads();
    int excl = v - s + (warp ? warpsum[warp - 1] : 0);
    g_off[2 * t] = excl;
    g_off[2 * t + 1] = excl + c0;
    if (t == 1023) g_off[Nn] = excl + s;
    __syncthreads();
    cnt[2 * t] = excl;
    cnt[2 * t + 1] = excl + c0;
    __syncthreads();
    for (int e = t; e < Ee; e += 1024) {
        int p = atomicAdd(&cnt[src[e]], 1);
        g_eidx[p] = e;
    }
}

// ================= prep: Wg split + C =================
__global__ void k_prep(const float* __restrict__ W3,
                       const float* __restrict__ b3,
                       const float* __restrict__ bng_g,
                       const float* __restrict__ bng_b,
                       const float* __restrict__ bnG_g,
                       const float* __restrict__ bnG_b) {
    int idx = blockIdx.x * blockDim.x + threadIdx.x;
    float rs = rsqrtf(1.f + EPSf);
    if (idx < 4096) {
        int d = idx >> 6, dp = idx & 63;
        float wg = (bng_g[d] * rs) * W3[idx] * (bnG_g[dp] * rs);
        uint32_t hi = f2tf(wg);
        g_wghi[idx] = hi;
        g_wglo[idx] = f2tf(wg - __uint_as_float(hi));
    } else if (idx < 4096 + 64) {
        int dp = idx - 4096;
        float s = 0.f;
        for (int d = 0; d < 64; d++) s += bng_b[d] * W3[d * 64 + dp];
        g_C[dp] = (s + b3[dp]) * (bnG_g[dp] * rs) + bnG_b[dp];
    }
}

// ================= node prep: LN(local[i]) -> u[i], v[i] =================
__global__ __launch_bounds__(256) void k_nodeprep(const float* __restrict__ local,
                                                  const float* __restrict__ ln_w,
                                                  const float* __restrict__ ln_b,
                                                  const float* __restrict__ conv_w) {
    __shared__ float lns[2][IND + 2];
    __shared__ float2 red[2][4];
    int tid = threadIdx.x;
    int grp = tid >> 7, t = tid & 127;
    int node = blockIdx.x * 2 + grp;
    int lane = t & 31, warp = t >> 5;

    float x = local[node * IND + t];
    float2 v = make_float2(x, x * x);
#pragma unroll
    for (int o = 16; o; o >>= 1) {
        v.x += __shfl_down_sync(0xffffffffu, v.x, o);
        v.y += __shfl_down_sync(0xffffffffu, v.y, o);
    }
    if (lane == 0) red[grp][warp] = v;
    if (t == 0) { lns[grp][0] = 0.f; lns[grp][IND + 1] = 0.f; }
    __syncthreads();
    float2 tot = red[grp][0];
    tot.x += red[grp][1].x + red[grp][2].x + red[grp][3].x;
    tot.y += red[grp][1].y + red[grp][2].y + red[grp][3].y;
    float mu = tot.x * (1.f / IND);
    float var = tot.y * (1.f / IND) - mu * mu;
    float ln = (x - mu) * rsqrtf(var + EPSf) * ln_w[t] + ln_b[t];
    lns[grp][t + 1] = ln;
    __syncthreads();
    float l0 = lns[grp][t], l1 = lns[grp][t + 1], l2 = lns[grp][t + 2];
    g_u[node * IND + t] = conv_w[0] * l0 + conv_w[1] * l1 + conv_w[2] * l2;
    g_v[node * IND + t] = conv_w[3] * l0 + conv_w[4] * l1 + conv_w[5] * l2;
}

// ================= p1 GEMM: packed-tf32 mma, no cvt in mainloop =================
// smem: Apk [128][36] uint4, Bpk [128][36] uint4, Ast [128][68] f32, Bst [64][136] f32
#define OFF_APK 0
#define OFF_BPK 73728
#define OFF_AST 147456
#define OFF_BST 182272
#define P1_SMEM 217088

__global__ __launch_bounds__(256) void k_p1pk(const float* __restrict__ h,
                                              const float* __restrict__ W1,
                                              const float* __restrict__ b1,
                                              const float* __restrict__ Wp2,
                                              const float* __restrict__ bp2) {
    extern __shared__ char smraw[];
    uint4* Apk = (uint4*)(smraw + OFF_APK);
    uint4* Bpk = (uint4*)(smraw + OFF_BPK);
    float* Ast = (float*)(smraw + OFF_AST);
    float* Bst = (float*)(smraw + OFF_BST);

    int tid = threadIdx.x;
    int wid = tid >> 5, lane = tid & 31;
    int g = lane >> 2, t = lane & 3;
    int warp_m = (wid >> 2) * 64;
    int warp_n = (wid & 3) * 32;
    int bx = blockIdx.x;
    int row0 = blockIdx.y * 128;
    int col0 = bx * 128;
    bool p2tile = (bx == 32);

    float acc[4][4][4];
#pragma unroll
    for (int mi = 0; mi < 4; mi++)
#pragma unroll
        for (int ni = 0; ni < 4; ni++)
#pragma unroll
            for (int r = 0; r < 4; r++) acc[mi][ni][r] = 0.f;

    for (int kc = 0; kc < IND; kc += 64) {
        // ---- stage f32 tiles (coalesced) ----
#pragma unroll
        for (int it = 0; it < 8; it++) {
            int chunk = tid + it * 256;
            int m = chunk >> 4;
            int k4 = (chunk & 15) * 4;
            float4 v = *(const float4*)&h[(row0 + m) * IND + kc + k4];
            *(float4*)&Ast[m * 68 + k4] = v;
        }
#pragma unroll
        for (int it = 0; it < 8; it++) {
            int chunk = tid + it * 256;
            int k = chunk >> 5;
            int n4 = (chunk & 31) * 4;
            float4 v;
            if (!p2tile) {
                v = *(const float4*)&W1[(kc + k) * NOUT + col0 + n4];
            } else if (n4 < 64) {
                v = *(const float4*)&Wp2[(kc + k) * HIDD + n4];
            } else {
                v = make_float4(0.f, 0.f, 0.f, 0.f);
            }
            *(float4*)&Bst[k * 136 + n4] = v;
        }
        __syncthreads();

        // ---- pack: convert once, store frag-aligned uint4 ----
        {
            int kb = tid >> 5;
            int rb = tid & 31;
#pragma unroll
            for (int jr = 0; jr < 4; jr++) {
                int row = rb + jr * 32;
                uint32_t hi[8], lo[8];
#pragma unroll
                for (int j = 0; j < 8; j++) {
                    float x = Ast[row * 68 + kb * 8 + j];
                    hi[j] = f2tf(x);
                    lo[j] = f2tf(x - __uint_as_float(hi[j]));
                }
#pragma unroll
                for (int tq = 0; tq < 4; tq++)
                    Apk[row * 36 + kb * 4 + tq] = make_uint4(hi[tq], hi[tq + 4], lo[tq], lo[tq + 4]);
            }
#pragma unroll
            for (int jn = 0; jn < 4; jn++) {
                int n = rb + jn * 32;
                uint32_t hi[8], lo[8];
#pragma unroll
                for (int j = 0; j < 8; j++) {
                    float x = Bst[(kb * 8 + j) * 136 + n];
                    hi[j] = f2tf(x);
                    lo[j] = f2tf(x - __uint_as_float(hi[j]));
                }
#pragma unroll
                for (int tq = 0; tq < 4; tq++)
                    Bpk[n * 36 + kb * 4 + tq] = make_uint4(hi[tq], hi[tq + 4], lo[tq], lo[tq + 4]);
            }
        }
        __syncthreads();

        // ---- mma mainloop: pure LDS.128 + HMMA ----
#pragma unroll 2
        for (int kb = 0; kb < 8; kb++) {
            uint4 afr[4][2];
            uint4 bfr[4];
#pragma unroll
            for (int mi = 0; mi < 4; mi++) {
                int r = warp_m + mi * 16 + g;
                afr[mi][0] = Apk[r * 36 + kb * 4 + t];
                afr[mi][1] = Apk[(r + 8) * 36 + kb * 4 + t];
            }
#pragma unroll
            for (int ni = 0; ni < 4; ni++) {
                int n = warp_n + ni * 8 + g;
                bfr[ni] = Bpk[n * 36 + kb * 4 + t];
            }
#pragma unroll
            for (int mi = 0; mi < 4; mi++) {
                uint32_t ah[4] = {afr[mi][0].x, afr[mi][1].x, afr[mi][0].y, afr[mi][1].y};
                uint32_t al[4] = {afr[mi][0].z, afr[mi][1].z, afr[mi][0].w, afr[mi][1].w};
#pragma unroll
                for (int ni = 0; ni < 4; ni++) {
                    uint32_t bh2[2] = {bfr[ni].x, bfr[ni].y};
                    uint32_t bl2[2] = {bfr[ni].z, bfr[ni].w};
                    mma_tf32(acc[mi][ni], ah, bh2);
                    mma_tf32(acc[mi][ni], ah, bl2);
                    mma_tf32(acc[mi][ni], al, bh2);
                }
            }
        }
        __syncthreads();
    }

    if (!p2tile) {
#pragma unroll
        for (int mi = 0; mi < 4; mi++) {
            int r = row0 + warp_m + mi * 16 + g;
#pragma unroll
            for (int ni = 0; ni < 4; ni++) {
                int c = col0 + warp_n + ni * 8 + t * 2;
                float2 bb = *(const float2*)&b1[c];
                float2 o0, o1;
                o0.x = fmaxf(acc[mi][ni][0] + bb.x, 0.f);
                o0.y = fmaxf(acc[mi][ni][1] + bb.y, 0.f);
                o1.x = fmaxf(acc[mi][ni][2] + bb.x, 0.f);
                o1.y = fmaxf(acc[mi][ni][3] + bb.y, 0.f);
                *(float2*)&g_p1[(size_t)r * NOUT + c] = o0;
                *(float2*)&g_p1[(size_t)(r + 8) * NOUT + c] = o1;
            }
        }
    } else {
#pragma unroll
        for (int mi = 0; mi < 4; mi++) {
            int r = row0 + warp_m + mi * 16 + g;
#pragma unroll
            for (int ni = 0; ni < 4; ni++) {
                int c = warp_n + ni * 8 + t * 2;
                if (c < HIDD) {
                    float2 bb = *(const float2*)&bp2[c];
                    float2 o0, o1;
                    o0.x = fmaxf(acc[mi][ni][0] + bb.x, 0.f);
                    o0.y = fmaxf(acc[mi][ni][1] + bb.y, 0.f);
                    o1.x = fmaxf(acc[mi][ni][2] + bb.x, 0.f);
                    o1.y = fmaxf(acc[mi][ni][3] + bb.y, 0.f);
                    *(float2*)&g_p2[r * HIDD + c] = o0;
                    *(float2*)&g_p2[(r + 8) * HIDD + c] = o1;
                }
            }
        }
    }
}

// ================= local branch v2 lean: gather u+v, relu, mma @W2 =================
#define TSTR2 132
#define W2ST  68
#define L2_SMEM (32 * TSTR2 * 4 + IND * W2ST * 4)   /* 16896 + 34816 = 51712 */

__global__ __launch_bounds__(256) void k_local2(const int* __restrict__ src,
                                                const int* __restrict__ dst,
                                                const float* __restrict__ conv_b,
                                                const float* __restrict__ W2,
                                                const float* __restrict__ b2,
                                                const float* __restrict__ bnL_g,
                                                const float* __restrict__ bnL_b,
                                                const float* __restrict__ ein,
                                                float* __restrict__ out) {
    extern __shared__ char smraw[];
    float* Ts = (float*)smraw;                       // [32][TSTR2]
    float* W2s = (float*)(smraw + 32 * TSTR2 * 4);   // [128][W2ST]

    int tid = threadIdx.x;
    int e0 = blockIdx.x * 32;
    float cb = conv_b[0];

#pragma unroll
    for (int it = 0; it < 16; it++) {
        int idx = tid + it * 256;
        int e = idx >> 7, tt = idx & 127;
        int se = src[e0 + e], de = dst[e0 + e];
        Ts[e * TSTR2 + tt] = fmaxf(g_u[se * IND + tt] + g_v[de * IND + tt] + cb, 0.f);
    }
#pragma unroll
    for (int it = 0; it < 8; it++) {
        int chunk = tid + it * 256;
        int k = chunk >> 4;
        int n4 = (chunk & 15) * 4;
        *(float4*)&W2s[k * W2ST + n4] = *(const float4*)&W2[k * HIDD + n4];
    }
    __syncthreads();

    int wid = tid >> 5, lane = tid & 31;
    int g = lane >> 2, t = lane & 3;
    int m0 = (wid & 1) * 16;
    int n0 = (wid >> 1) * 16;

    float acc[2][4];
#pragma unroll
    for (int ni = 0; ni < 2; ni++)
#pragma unroll
        for (int r = 0; r < 4; r++) acc[ni][r] = 0.f;

#pragma unroll 4
    for (int ks = 0; ks < 128; ks += 8) {
        uint32_t ahi[4], alo[4], bh[2][2], bl[2][2];
        int r = m0 + g;
        float a0 = Ts[r * TSTR2 + ks + t];
        float a1 = Ts[(r + 8) * TSTR2 + ks + t];
        float a2 = Ts[r * TSTR2 + ks + t + 4];
        float a3 = Ts[(r + 8) * TSTR2 + ks + t + 4];
        ahi[0] = f2tf(a0); alo[0] = f2tf(a0 - __uint_as_float(ahi[0]));
        ahi[1] = f2tf(a1); alo[1] = f2tf(a1 - __uint_as_float(ahi[1]));
        ahi[2] = f2tf(a2); alo[2] = f2tf(a2 - __uint_as_float(ahi[2]));
        ahi[3] = f2tf(a3); alo[3] = f2tf(a3 - __uint_as_float(ahi[3]));
#pragma unroll
        for (int ni = 0; ni < 2; ni++) {
            int n = n0 + ni * 8 + g;
            float w0 = W2s[(ks + t) * W2ST + n];
            float w1 = W2s[(ks + t + 4) * W2ST + n];
            bh[ni][0] = f2tf(w0); bl[ni][0] = f2tf(w0 - __uint_as_float(bh[ni][0]));
            bh[ni][1] = f2tf(w1); bl[ni][1] = f2tf(w1 - __uint_as_float(bh[ni][1]));
        }
#pragma unroll
        for (int ni = 0; ni < 2; ni++) {
            mma_tf32(acc[ni], ahi, bh[ni]);
            mma_tf32(acc[ni], ahi, bl[ni]);
            mma_tf32(acc[ni], alo, bh[ni]);
        }
    }

    float rs = rsqrtf(1.f + EPSf);
    int ea = e0 + m0 + g, eb = ea + 8;
#pragma unroll
    for (int ni = 0; ni < 2; ni++) {
        int c = n0 + ni * 8 + t * 2;
        float2 bb = *(const float2*)&b2[c];
        float2 gg = *(const float2*)&bnL_g[c];
        float2 bL = *(const float2*)&bnL_b[c];
        float2 ia = *(const float2*)&ein[ea * HIDD + c];
        float2 ib = *(const float2*)&ein[eb * HIDD + c];
        float2 oa, ob;
        oa.x = fmaxf((acc[ni][0] + bb.x) * (gg.x * rs) + bL.x, 0.f) + ia.x;
        oa.y = fmaxf((acc[ni][1] + bb.y) * (gg.y * rs) + bL.y, 0.f) + ia.y;
        ob.x = fmaxf((acc[ni][2] + bb.x) * (gg.x * rs) + bL.x, 0.f) + ib.x;
        ob.y = fmaxf((acc[ni][3] + bb.y) * (gg.y * rs) + bL.y, 0.f) + ib.y;
        *(float2*)&out[ea * HIDD + c] = oa;
        *(float2*)&out[eb * HIDD + c] = ob;
    }
}

// ================= global branch fused =================
#define GA_STR 68
#define ECAP 64
#define GO_AS  0
#define GO_BHI (64 * GA_STR * 4)
#define GO_BLO (GO_BHI + 64 * 72 * 4)
#define GO_P2  (GO_BLO + 64 * 72 * 4)
#define GO_EIX (GO_P2 + ECAP * 64 * 4)
#define G2_SMEM (GO_EIX + ECAP * 4)

__global__ __launch_bounds__(256) void k_global2(const int* __restrict__ dst,
                                                 float* __restrict__ out) {
    extern __shared__ char smraw[];
    float* As = (float*)(smraw + GO_AS);
    float* Gs = As;
    uint32_t* Bhi = (uint32_t*)(smraw + GO_BHI);
    uint32_t* Blo = (uint32_t*)(smraw + GO_BLO);
    float* p2buf = (float*)(smraw + GO_P2);
    int* eixs = (int*)(smraw + GO_EIX);

    int node = blockIdx.x;
    int tid = threadIdx.x;
    int beg = g_off[node], end = g_off[node + 1];
    if (beg == end) return;

    int ec = min(end - beg, ECAP);
    for (int idx = tid; idx < ec * 64; idx += 256) {
        int ei = idx >> 6, d2 = idx & 63;
        int e = g_eidx[beg + ei];
        if (d2 == 0) eixs[ei] = e;
        p2buf[idx] = g_p2[dst[e] * HIDD + d2];
    }

    const float* p1row = &g_p1[(size_t)node * NOUT];
#pragma unroll
    for (int it = 0; it < 16; it++) {
        int idx = tid + it * 256;
        int d = idx >> 6, k = idx & 63;
        As[k * GA_STR + d] = p1row[idx];
    }
#pragma unroll
    for (int it = 0; it < 16; it++) {
        int idx = tid + it * 256;
        int d = idx >> 6, dp = idx & 63;
        Bhi[d * 72 + dp] = g_wghi[idx];
        Blo[d * 72 + dp] = g_wglo[idx];
    }
    __syncthreads();

    int wid = tid >> 5, lane = tid & 31;
    int g = lane >> 2, t = lane & 3;
    int m0 = (wid & 3) * 16;
    int n0 = (wid >> 2) * 32;

    float acc[4][4];
#pragma unroll
    for (int ni = 0; ni < 4; ni++)
#pragma unroll
        for (int r = 0; r < 4; r++) acc[ni][r] = 0.f;

#pragma unroll
    for (int ks = 0; ks < 64; ks += 8) {
        uint32_t ahi[4], alo[4], bh[4][2], bl[4][2];
        int r = m0 + g;
        float a0 = As[r * GA_STR + ks + t];
        float a1 = As[(r + 8) * GA_STR + ks + t];
        float a2 = As[r * GA_STR + ks + t + 4];
        float a3 = As[(r + 8) * GA_STR + ks + t + 4];
        ahi[0] = f2tf(a0); alo[0] = f2tf(a0 - __uint_as_float(ahi[0]));
        ahi[1] = f2tf(a1); alo[1] = f2tf(a1 - __uint_as_float(ahi[1]));
        ahi[2] = f2tf(a2); alo[2] = f2tf(a2 - __uint_as_float(ahi[2]));
        ahi[3] = f2tf(a3); alo[3] = f2tf(a3 - __uint_as_float(ahi[3]));
#pragma unroll
        for (int ni = 0; ni < 4; ni++) {
            int n = n0 + ni * 8 + g;
            bh[ni][0] = Bhi[(ks + t) * 72 + n];
            bh[ni][1] = Bhi[(ks + t + 4) * 72 + n];
            bl[ni][0] = Blo[(ks + t) * 72 + n];
            bl[ni][1] = Blo[(ks + t + 4) * 72 + n];
        }
#pragma unroll
        for (int ni = 0; ni < 4; ni++) {
            mma_tf32(acc[ni], ahi, bh[ni]);
            mma_tf32(acc[ni], ahi, bl[ni]);
            mma_tf32(acc[ni], alo, bh[ni]);
        }
    }
    __syncthreads();

    int m = m0 + g;
#pragma unroll
    for (int ni = 0; ni < 4; ni++) {
        int n = n0 + ni * 8 + t * 2;
        Gs[m * 65 + n] = acc[ni][0];
        Gs[m * 65 + n + 1] = acc[ni][1];
        Gs[(m + 8) * 65 + n] = acc[ni][2];
        Gs[(m + 8) * 65 + n + 1] = acc[ni][3];
    }
    __syncthreads();

    int d = tid & 63, grp = tid >> 6;
    float Gr[64];
#pragma unroll
    for (int k = 0; k < 64; k++) Gr[k] = Gs[k * 65 + d];
    float Cd = g_C[d];

    int base = beg;
    while (true) {
        for (int e = grp; e < ec; e += 4) {
            const float4* p = (const float4*)&p2buf[e * 64];
            float a2 = 0.f;
#pragma unroll
            for (int k4 = 0; k4 < 16; k4++) {
                float4 v = p[k4];
                a2 += Gr[k4 * 4 + 0] * v.x + Gr[k4 * 4 + 1] * v.y
                    + Gr[k4 * 4 + 2] * v.z + Gr[k4 * 4 + 3] * v.w;
            }
            int eg = eixs[e];
            out[eg * HIDD + d] += fmaxf(a2 + Cd, 0.f);
        }
        base += ec;
        if (base >= end) break;
        __syncthreads();
        ec = min(end - base, ECAP);
        for (int idx = tid; idx < ec * 64; idx += 256) {
            int ei = idx >> 6, d2 = idx & 63;
            int e = g_eidx[base + ei];
            if (d2 == 0) eixs[ei] = e;
            p2buf[idx] = g_p2[dst[e] * HIDD + d2];
        }
        __syncthreads();
    }
}

// ================= launch =================
extern "C" void kernel_launch(void* const* d_in, const int* in_sizes, int n_in,
                              void* d_out, int out_size) {
    const float* h      = (const float*)d_in[0];
    const float* local_ = (const float*)d_in[1];
    const float* ein    = (const float*)d_in[2];
    const int*   src    = (const int*)d_in[3];
    const int*   dst    = (const int*)d_in[4];
    const float* ln_w   = (const float*)d_in[5];
    const float* ln_b   = (const float*)d_in[6];
    const float* conv_w = (const float*)d_in[7];
    const float* conv_b = (const float*)d_in[8];
    const float* W1     = (const float*)d_in[9];
    const float* b1     = (const float*)d_in[10];
    const float* Wp2    = (const float*)d_in[11];
    const float* bp2    = (const float*)d_in[12];
    const float* W2     = (const float*)d_in[13];
    const float* b2     = (const float*)d_in[14];
    const float* W3     = (const float*)d_in[15];
    const float* b3     = (const float*)d_in[16];
    const float* bng_g  = (const float*)d_in[17];
    const float* bng_b  = (const float*)d_in[18];
    const float* bnG_g  = (const float*)d_in[19];
    const float* bnG_b  = (const float*)d_in[20];
    const float* bnL_g  = (const float*)d_in[21];
    const float* bnL_b  = (const float*)d_in[22];
    float* out = (float*)d_out;

    static int smem_set = 0;
    if (!smem_set) {
        cudaFuncSetAttribute(k_p1pk, cudaFuncAttributeMaxDynamicSharedMemorySize, P1_SMEM);
        cudaFuncSetAttribute(k_local2, cudaFuncAttributeMaxDynamicSharedMemorySize, L2_SMEM);
        cudaFuncSetAttribute(k_global2, cudaFuncAttributeMaxDynamicSharedMemorySize, G2_SMEM);
        smem_set = 1;
    }

    k_bucket<<<1, 1024>>>(src);
    k_prep<<<17, 256>>>(W3, b3, bng_g, bng_b, bnG_g, bnG_b);
    k_nodeprep<<<Nn / 2, 256>>>(local_, ln_w, ln_b, conv_w);
    k_local2<<<Ee / 32, 256, L2_SMEM>>>(src, dst, conv_b, W2, b2, bnL_g, bnL_b,
                                        ein, out);              // 4th -> profiled
    k_p1pk<<<dim3(33, Nn / 128), 256, P1_SMEM>>>(h, W1, b1, Wp2, bp2);
    k_global2<<<Nn, 256, G2_SMEM>>>(dst, out);
}